// round 13
// baseline (speedup 1.0000x reference)
#include <cuda_runtime.h>
#include <cuda_bf16.h>
#include <cstdint>
#include <math.h>

// Problem constants
#define Bq   4
#define Nq   2048
#define Cq   1024
#define Hq   16
#define Dq   64
#define Rq   16
#define Mq   (Bq*Nq)          // 8192 rows
#define C3q  (3*Cq)           // 3072
#define SCALEF 0.125f         // 1/sqrt(64)
#define L2E 1.4426950408889634f

// ---------------------------------------------------------------------------
// Device-global scratch
// ---------------------------------------------------------------------------
__device__ __nv_bfloat16 g_qh[Mq*Cq], g_ql[Mq*Cq];    // q (pre-scaled) [B,H,N,D]
__device__ __nv_bfloat16 g_kh[Mq*Cq], g_kl[Mq*Cq];    // k
__device__ __nv_bfloat16 g_vh[Mq*Cq], g_vl[Mq*Cq];    // v
__device__ __nv_bfloat16 g_aoh[Mq*Cq], g_aol[Mq*Cq];  // attn out [B,N,C] split

__device__ __nv_bfloat16 g_Ah[Mq*Cq],  g_Al[Mq*Cq];    // qkv A split [M,K]
__device__ __nv_bfloat16 g_Bh[C3q*Cq], g_Bl[C3q*Cq];   // W^T split [N,K]

// ---------------------------------------------------------------------------
// helpers
// ---------------------------------------------------------------------------
__device__ __forceinline__ uint32_t smem_to_u32(const void* p) {
    uint32_t a;
    asm("{ .reg .u64 t; cvta.to.shared.u64 t, %1; cvt.u32.u64 %0, t; }"
        : "=r"(a) : "l"(p));
    return a;
}
__device__ __forceinline__ void ldsm_x4(uint32_t* r, uint32_t addr) {
    asm volatile("ldmatrix.sync.aligned.m8n8.x4.shared.b16 {%0,%1,%2,%3}, [%4];"
                 : "=r"(r[0]), "=r"(r[1]), "=r"(r[2]), "=r"(r[3]) : "r"(addr));
}
__device__ __forceinline__ void ldsm_x4_t(uint32_t* r, uint32_t addr) {
    asm volatile("ldmatrix.sync.aligned.m8n8.x4.trans.shared.b16 {%0,%1,%2,%3}, [%4];"
                 : "=r"(r[0]), "=r"(r[1]), "=r"(r[2]), "=r"(r[3]) : "r"(addr));
}
__device__ __forceinline__ void mma16816(float* c, const uint32_t* a, const uint32_t* b) {
    asm volatile("mma.sync.aligned.m16n8k16.row.col.f32.bf16.bf16.f32 "
        "{%0,%1,%2,%3}, {%4,%5,%6,%7}, {%8,%9}, {%0,%1,%2,%3};"
        : "+f"(c[0]), "+f"(c[1]), "+f"(c[2]), "+f"(c[3])
        : "r"(a[0]), "r"(a[1]), "r"(a[2]), "r"(a[3]), "r"(b[0]), "r"(b[1]));
}
__device__ __forceinline__ void split2(float x, float y, uint32_t& hi, uint32_t& lo) {
    __nv_bfloat16 hx = __float2bfloat16(x), hy = __float2bfloat16(y);
    __nv_bfloat16 lx = __float2bfloat16(x - __bfloat162float(hx));
    __nv_bfloat16 ly = __float2bfloat16(y - __bfloat162float(hy));
    __nv_bfloat162 H(hx, hy), L(lx, ly);
    hi = *(uint32_t*)&H; lo = *(uint32_t*)&L;
}
__device__ __forceinline__ void cp_async16(uint32_t dst, const void* src) {
    asm volatile("cp.async.cg.shared.global [%0], [%1], 16;"
                 :: "r"(dst), "l"(src) : "memory");
}
__device__ __forceinline__ void cp_commit() {
    asm volatile("cp.async.commit_group;" ::: "memory");
}
template<int N> __device__ __forceinline__ void cp_wait() {
    asm volatile("cp.async.wait_group %0;" :: "n"(N) : "memory");
}
__device__ __forceinline__ float ex2(float x) {
    float y; asm("ex2.approx.f32 %0, %1;" : "=f"(y) : "f"(x)); return y;
}
// swizzled byte offset inside a (128B-row) bf16 tile; ch = 16B chunk 0..7
__device__ __forceinline__ uint32_t swz_bf16(int row, int ch) {
    return (uint32_t)(row * 128 + ((ch ^ (row & 7)) << 4));
}
// swizzled byte offset inside a (256B-row) f32 tile; ch = 16B chunk 0..15
__device__ __forceinline__ uint32_t swz_f32(int row, int ch) {
    return (uint32_t)(row * 256 + (((ch ^ ((row & 7) << 1)) & 15) << 4));
}

// ---------------------------------------------------------------------------
// Conversion kernels
// ---------------------------------------------------------------------------
__global__ void split_kernel(const float* __restrict__ X,
                             __nv_bfloat16* __restrict__ H,
                             __nv_bfloat16* __restrict__ L) {
    int i = blockIdx.x * blockDim.x + threadIdx.x;
    float4 x = ((const float4*)X)[i];
    uint32_t h0, l0, h1, l1;
    split2(x.x, x.y, h0, l0);
    split2(x.z, x.w, h1, l1);
    ((uint32_t*)H)[2*i+0] = h0; ((uint32_t*)H)[2*i+1] = h1;
    ((uint32_t*)L)[2*i+0] = l0; ((uint32_t*)L)[2*i+1] = l1;
}

__global__ void transpose_split_kernel(const float* __restrict__ W,
                                       __nv_bfloat16* __restrict__ BH,
                                       __nv_bfloat16* __restrict__ BL,
                                       int K, int N) {
    __shared__ float tile[32][33];
    int n0 = blockIdx.x * 32, k0 = blockIdx.y * 32;
    int tx = threadIdx.x, ty = threadIdx.y;
#pragma unroll
    for (int i = 0; i < 4; i++)
        tile[ty + i * 8][tx] = W[(size_t)(k0 + ty + i * 8) * N + n0 + tx];
    __syncthreads();
#pragma unroll
    for (int i = 0; i < 4; i++) {
        int nl = ty + i * 8;
        float v = tile[tx][nl];
        __nv_bfloat16 h = __float2bfloat16(v);
        __nv_bfloat16 l = __float2bfloat16(v - __bfloat162float(h));
        size_t o = (size_t)(n0 + nl) * K + k0 + tx;
        BH[o] = h; BL[o] = l;
    }
}

// W_qkv[K,3C] -> [3C,K] transpose + split with LoRA delta folded into q cols
__global__ void transpose_split_qkv_kernel(const float* __restrict__ W,
                                           const float* __restrict__ WA,
                                           const float* __restrict__ WB,
                                           const float* __restrict__ mag,
                                           __nv_bfloat16* __restrict__ BH,
                                           __nv_bfloat16* __restrict__ BL) {
    __shared__ float tile[32][33];
    __shared__ float WAs[32][17];   // [k][r]
    __shared__ float WBs[16][33];   // [r][n] (mag applied)
    int n0 = blockIdx.x * 32, k0 = blockIdx.y * 32;
    int tx = threadIdx.x, ty = threadIdx.y;
    const bool doq = (n0 < Cq);
#pragma unroll
    for (int i = 0; i < 4; i++)
        tile[ty + i * 8][tx] = W[(size_t)(k0 + ty + i * 8) * C3q + n0 + tx];
    if (doq) {
        int fi = ty * 32 + tx;
#pragma unroll
        for (int i = 0; i < 2; i++) {
            int idx = fi + i * 256;
            int kr = idx >> 4, r = idx & 15;
            WAs[kr][r] = WA[(size_t)(k0 + kr) * Rq + r];
            int rr = idx >> 5, nn = idx & 31;
            WBs[rr][nn] = mag[(n0 + nn) >> 6] * WB[(size_t)rr * Cq + n0 + nn];
        }
    }
    __syncthreads();
#pragma unroll
    for (int i = 0; i < 4; i++) {
        int nl = ty + i * 8;
        float v = tile[tx][nl];
        if (doq) {
            float d = 0.f;
#pragma unroll
            for (int r = 0; r < Rq; r++) d += WAs[tx][r] * WBs[r][nl];
            v += d;
        }
        __nv_bfloat16 h = __float2bfloat16(v);
        __nv_bfloat16 l = __float2bfloat16(v - __bfloat162float(h));
        size_t o = (size_t)(n0 + nl) * Cq + k0 + tx;
        BH[o] = h; BL[o] = l;
    }
}

// ---------------------------------------------------------------------------
// mma.sync split-bf16 GEMM, 2 CTAs/SM (unchanged from R12 except q pre-scale).
// ---------------------------------------------------------------------------
#define GSTAGE 49152
#define NKB    16
#define SMEM_GEMM (2 * GSTAGE)              // 98304 B

template<int MODE>
__global__ __launch_bounds__(128, 2) void mma_gemm_kernel(
    const __nv_bfloat16* __restrict__ Ah, const __nv_bfloat16* __restrict__ Al,
    const __nv_bfloat16* __restrict__ Bh, const __nv_bfloat16* __restrict__ Bl,
    float* __restrict__ out)
{
    extern __shared__ char smg[];
    const uint32_t sb = smem_to_u32(smg);

    const int bn = blockIdx.x * 128;
    const int bm = blockIdx.y * 64;
    const int t    = threadIdx.x;
    const int lane = t & 31;
    const int wid  = t >> 5;
    const int wm = wid & 1, wn = wid >> 1;

    const int a_row = lane & 15;
    const int a_ch  = lane >> 4;
    const int b_row = (lane & 7) + ((lane & 16) ? 8 : 0);
    const int b_ch  = (lane & 8) >> 3;

    auto load_stage = [&](int s, int kb) {
        uint32_t sbase = sb + (uint32_t)(s * GSTAGE);
#pragma unroll
        for (int it = 0; it < 4; it++) {
            int idx = t + it * 128;
            int row = idx >> 3, ch = idx & 7;
            size_t ga = (size_t)(bm + row) * Cq + kb * 64 + ch * 8;
            uint32_t o = sbase + swz_bf16(row, ch);
            cp_async16(o,        &Ah[ga]);
            cp_async16(o + 8192, &Al[ga]);
        }
#pragma unroll
        for (int it = 0; it < 8; it++) {
            int idx = t + it * 128;
            int row = idx >> 3, ch = idx & 7;
            size_t gb = (size_t)(bn + row) * Cq + kb * 64 + ch * 8;
            uint32_t o = sbase + 16384 + swz_bf16(row, ch);
            cp_async16(o,         &Bh[gb]);
            cp_async16(o + 16384, &Bl[gb]);
        }
        cp_commit();
    };

    float c[16][4];
#pragma unroll
    for (int i = 0; i < 16; i++)
#pragma unroll
        for (int j = 0; j < 4; j++) c[i][j] = 0.f;

    load_stage(0, 0);

    for (int kb = 0; kb < NKB; kb++) {
        const int s = kb & 1;
        if (kb + 1 < NKB) { load_stage(s ^ 1, kb + 1); cp_wait<1>(); }
        else              { cp_wait<0>(); }
        __syncthreads();

        const uint32_t sbase = sb + (uint32_t)(s * GSTAGE);

#pragma unroll
        for (int kk = 0; kk < 4; kk++) {
            uint32_t ah[2][4], al[2][4];
#pragma unroll
            for (int fm = 0; fm < 2; fm++) {
                uint32_t off = swz_bf16(wm * 32 + fm * 16 + a_row, kk * 2 + a_ch);
                ldsm_x4(ah[fm], sbase + off);
                ldsm_x4(al[fm], sbase + 8192 + off);
            }
#pragma unroll
            for (int fn2 = 0; fn2 < 4; fn2++) {
                uint32_t off = swz_bf16(wn * 64 + fn2 * 16 + b_row, kk * 2 + b_ch);
                uint32_t bh4[4], bl4[4];
                ldsm_x4(bh4, sbase + 16384 + off);
                ldsm_x4(bl4, sbase + 32768 + off);
#pragma unroll
                for (int fm = 0; fm < 2; fm++) {
                    float* c0 = c[fm * 8 + fn2 * 2 + 0];
                    float* c1 = c[fm * 8 + fn2 * 2 + 1];
                    mma16816(c0, ah[fm], &bh4[0]);
                    mma16816(c1, ah[fm], &bh4[2]);
                    mma16816(c0, ah[fm], &bl4[0]);
                    mma16816(c1, ah[fm], &bl4[2]);
                    mma16816(c0, al[fm], &bh4[0]);
                    mma16816(c1, al[fm], &bh4[2]);
                }
            }
        }
        __syncthreads();
    }

    // Epilogue (q gets SCALEF folded in so attention skips the scale)
#pragma unroll
    for (int fm = 0; fm < 2; fm++) {
#pragma unroll
        for (int fn = 0; fn < 8; fn++) {
            const float* cc = c[fm * 8 + fn];
            int r0  = bm + wm * 32 + fm * 16 + (lane >> 2);
            int col = bn + wn * 64 + fn * 8 + (lane & 3) * 2;
#pragma unroll
            for (int half = 0; half < 2; half++) {
                int m = r0 + half * 8;
                float vx = cc[half * 2 + 0], vy = cc[half * 2 + 1];
                if (MODE == 1) {
                    *(float2*)(out + (size_t)m * Cq + col) = make_float2(vx, vy);
                } else {
                    int sel = col >> 10;
                    int within = col & (Cq - 1);
                    int h = within >> 6, d = within & 63;
                    int b = m >> 11, n = m & (Nq - 1);
                    size_t oidx = ((((size_t)b * Hq + h) * Nq) + n) * Dq + d;
                    if (sel == 0) { vx *= SCALEF; vy *= SCALEF; }
                    uint32_t hi, lo;
                    split2(vx, vy, hi, lo);
                    __nv_bfloat16 *ph, *pl;
                    if (sel == 0)      { ph = g_qh; pl = g_ql; }
                    else if (sel == 1) { ph = g_kh; pl = g_kl; }
                    else               { ph = g_vh; pl = g_vl; }
                    *(uint32_t*)&ph[oidx] = hi;
                    *(uint32_t*)&pl[oidx] = lo;
                }
            }
        }
    }
}

// ---------------------------------------------------------------------------
// Flash attention, split-bf16, 2 CTAs/SM. R12 structure with a shortened
// softmax critical path: S accumulators initialized from the mask (scale
// pre-folded into q), exp via raw ex2.approx (one FMA per element), and
// conditional O-rescale (skipped when the running max didn't change).
// ---------------------------------------------------------------------------
#define KVB2      8192
#define AQ_BYTES  16384
#define AKV_BYTES (2 * 4 * KVB2)
#define AMSK_OFF  (AQ_BYTES + AKV_BYTES)
#define AMSK_STAGE 16384
#define SMEM_ATTN (AMSK_OFF + 2 * AMSK_STAGE) // 114688 B

__global__ __launch_bounds__(128, 2) void attn_mma_kernel(const float* __restrict__ mask) {
    extern __shared__ char smc[];
    const uint32_t sb    = smem_to_u32(smc);
    const uint32_t sbQh  = sb;
    const uint32_t sbQl  = sb + 8192;
    const uint32_t sbKV  = sb + AQ_BYTES;
    const uint32_t sbMsk = sb + AMSK_OFF;

    const int h  = blockIdx.x, qt = blockIdx.y, b = blockIdx.z;
    const int t    = threadIdx.x;
    const int lane = t & 31;
    const int wid  = t >> 5;

    const size_t base = ((size_t)b * Hq + h) * Nq;
    const float* maskbase = mask + (size_t)b * Nq * Nq + (size_t)(qt * 64) * Nq;

    auto load_stage = [&](int s, int kt) {
#pragma unroll
        for (int it = 0; it < 4; it++) {
            int idx = t + it * 128;
            int row = idx >> 3, ch = idx & 7;
            size_t g = (base + (size_t)(kt * 64 + row)) * Dq + ch * 8;
            uint32_t o = sbKV + (uint32_t)(s * 4 * KVB2) + swz_bf16(row, ch);
            cp_async16(o + 0 * KVB2, &g_kh[g]);
            cp_async16(o + 1 * KVB2, &g_kl[g]);
            cp_async16(o + 2 * KVB2, &g_vh[g]);
            cp_async16(o + 3 * KVB2, &g_vl[g]);
        }
#pragma unroll
        for (int it = 0; it < 8; it++) {
            int idx = t + it * 128;
            int row = idx >> 4, ch = idx & 15;
            const float* src = maskbase + (size_t)row * Nq + kt * 64 + ch * 4;
            uint32_t dst = sbMsk + (uint32_t)(s * AMSK_STAGE) + swz_f32(row, ch);
            cp_async16(dst, src);
        }
        cp_commit();
    };

    load_stage(0, 0);

    const __nv_bfloat16* Qgh = g_qh + (base + (size_t)qt * 64) * Dq;
    const __nv_bfloat16* Qgl = g_ql + (base + (size_t)qt * 64) * Dq;
#pragma unroll
    for (int it = 0; it < 4; it++) {
        int idx = t + it * 128;
        int row = idx >> 3, ch = idx & 7;
        uint32_t o = swz_bf16(row, ch);
        *(uint4*)(smc + o)        = *(const uint4*)&Qgh[row * Dq + ch * 8];
        *(uint4*)(smc + 8192 + o) = *(const uint4*)&Qgl[row * Dq + ch * 8];
    }
    __syncthreads();

    const int a_row = lane & 15;
    const int a_ch  = (lane >> 4);
    uint32_t aQh[4][4], aQl[4][4];
    {
        int qrow = wid * 16 + a_row;
#pragma unroll
        for (int kk = 0; kk < 4; kk++) {
            uint32_t off = swz_bf16(qrow, kk * 2 + a_ch);
            ldsm_x4(aQh[kk], sbQh + off);
            ldsm_x4(aQl[kk], sbQl + off);
        }
    }

    const int b_row = (lane & 7) + ((lane & 16) ? 8 : 0);
    const int b_ch  = (lane & 8) >> 3;
    const int v_row = lane & 15;
    const int v_ch  = (lane & 16) ? 1 : 0;

    float o[8][4];
#pragma unroll
    for (int i = 0; i < 8; i++)
#pragma unroll
        for (int j = 0; j < 4; j++) o[i][j] = 0.f;
    float m0 = -1e30f, m1 = -1e30f, l0 = 0.f, l1 = 0.f;

    const int rloc0 = wid * 16 + (lane >> 2);
    const int mcol  = 2 * (lane & 3);

    for (int kt = 0; kt < Nq / 64; kt++) {
        const int s = kt & 1;
        if (kt + 1 < Nq / 64) { load_stage(s ^ 1, kt + 1); cp_wait<1>(); }
        else                  { cp_wait<0>(); }
        __syncthreads();

        const uint32_t sbKh = sbKV + (uint32_t)(s * 4 * KVB2);
        const uint32_t sbKl = sbKh + KVB2;
        const uint32_t sbVh = sbKh + 2 * KVB2;
        const uint32_t sbVl = sbKh + 3 * KVB2;
        const char* mskC = smc + AMSK_OFF + s * AMSK_STAGE;

        // Init S accumulators from mask (q pre-scaled, so S+mask = logits)
        float c[8][4];
#pragma unroll
        for (int f = 0; f < 8; f++) {
            int col = f * 8 + mcol;
            int ch  = col >> 2;
            int wo  = (col & 3) * 4;
            float2 mk0 = *(const float2*)(mskC + swz_f32(rloc0,     ch) + wo);
            float2 mk1 = *(const float2*)(mskC + swz_f32(rloc0 + 8, ch) + wo);
            c[f][0] = mk0.x; c[f][1] = mk0.y;
            c[f][2] = mk1.x; c[f][3] = mk1.y;
        }

        // S += Q K^T (16 x 64 per warp), 3-term split (fn2 outer)
#pragma unroll
        for (int fn2 = 0; fn2 < 4; fn2++) {
#pragma unroll
            for (int kk = 0; kk < 4; kk++) {
                uint32_t off = swz_bf16(fn2 * 16 + b_row, kk * 2 + b_ch);
                uint32_t bh4[4], bl4[4];
                ldsm_x4(bh4, sbKh + off);
                ldsm_x4(bl4, sbKl + off);
                float* c0 = c[fn2 * 2 + 0];
                float* c1 = c[fn2 * 2 + 1];
                mma16816(c0, aQh[kk], &bh4[0]);
                mma16816(c1, aQh[kk], &bh4[2]);
                mma16816(c0, aQh[kk], &bl4[0]);
                mma16816(c1, aQh[kk], &bl4[2]);
                mma16816(c0, aQl[kk], &bh4[0]);
                mma16816(c1, aQl[kk], &bh4[2]);
            }
        }

        // online softmax (exp2-based; max over quad; l per-lane)
        float rm0 = -1e30f, rm1 = -1e30f;
#pragma unroll
        for (int f = 0; f < 8; f++) {
            rm0 = fmaxf(rm0, fmaxf(c[f][0], c[f][1]));
            rm1 = fmaxf(rm1, fmaxf(c[f][2], c[f][3]));
        }
        rm0 = fmaxf(rm0, __shfl_xor_sync(0xffffffffu, rm0, 1));
        rm0 = fmaxf(rm0, __shfl_xor_sync(0xffffffffu, rm0, 2));
        rm1 = fmaxf(rm1, __shfl_xor_sync(0xffffffffu, rm1, 1));
        rm1 = fmaxf(rm1, __shfl_xor_sync(0xffffffffu, rm1, 2));
        float nm0 = fmaxf(m0, rm0), nm1 = fmaxf(m1, rm1);
        float b0 = nm0 * L2E, b1 = nm1 * L2E;
        float sc0 = ex2(fmaf(m0, L2E, -b0));
        float sc1 = ex2(fmaf(m1, L2E, -b1));
        float s0 = 0.f, s1 = 0.f;
#pragma unroll
        for (int f = 0; f < 8; f++) {
            c[f][0] = ex2(fmaf(c[f][0], L2E, -b0));
            c[f][1] = ex2(fmaf(c[f][1], L2E, -b0));
            c[f][2] = ex2(fmaf(c[f][2], L2E, -b1));
            c[f][3] = ex2(fmaf(c[f][3], L2E, -b1));
            s0 += c[f][0] + c[f][1];
            s1 += c[f][2] + c[f][3];
        }
        l0 = l0 * sc0 + s0; m0 = nm0;
        l1 = l1 * sc1 + s1; m1 = nm1;
        if (sc0 != 1.0f) {
#pragma unroll
            for (int f = 0; f < 8; f++) { o[f][0] *= sc0; o[f][1] *= sc0; }
        }
        if (sc1 != 1.0f) {
#pragma unroll
            for (int f = 0; f < 8; f++) { o[f][2] *= sc1; o[f][3] *= sc1; }
        }

        // O += P V
#pragma unroll
        for (int kk = 0; kk < 4; kk++) {
            uint32_t pah[4], pal[4];
            split2(c[2*kk  ][0], c[2*kk  ][1], pah[0], pal[0]);
            split2(c[2*kk  ][2], c[2*kk  ][3], pah[1], pal[1]);
            split2(c[2*kk+1][0], c[2*kk+1][1], pah[2], pal[2]);
            split2(c[2*kk+1][2], c[2*kk+1][3], pah[3], pal[3]);
#pragma unroll
            for (int nn = 0; nn < 4; nn++) {
                uint32_t off = swz_bf16(kk * 16 + v_row, nn * 2 + v_ch);
                uint32_t vh4[4], vl4[4];
                ldsm_x4_t(vh4, sbVh + off);
                ldsm_x4_t(vl4, sbVl + off);
                float* o0 = o[nn * 2 + 0];
                float* o1 = o[nn * 2 + 1];
                mma16816(o0, pah, &vh4[0]);
                mma16816(o1, pah, &vh4[2]);
                mma16816(o0, pah, &vl4[0]);
                mma16816(o1, pah, &vl4[2]);
                mma16816(o0, pal, &vh4[0]);
                mma16816(o1, pal, &vh4[2]);
            }
        }
        __syncthreads();
    }

    // Final quad-reduce of l
    l0 += __shfl_xor_sync(0xffffffffu, l0, 1);
    l0 += __shfl_xor_sync(0xffffffffu, l0, 2);
    l1 += __shfl_xor_sync(0xffffffffu, l1, 1);
    l1 += __shfl_xor_sync(0xffffffffu, l1, 2);

    // Epilogue
    float inv0 = 1.0f / l0, inv1 = 1.0f / l1;
    int n0r = qt * 64 + wid * 16 + (lane >> 2);
#pragma unroll
    for (int f = 0; f < 8; f++) {
        int colc = h * Dq + f * 8 + 2 * (lane & 3);
        size_t i0 = ((size_t)(b * Nq + n0r)) * Cq + colc;
        size_t i1 = ((size_t)(b * Nq + n0r + 8)) * Cq + colc;
        uint32_t hi, lo;
        split2(o[f][0] * inv0, o[f][1] * inv0, hi, lo);
        *(uint32_t*)&g_aoh[i0] = hi; *(uint32_t*)&g_aol[i0] = lo;
        split2(o[f][2] * inv1, o[f][3] * inv1, hi, lo);
        *(uint32_t*)&g_aoh[i1] = hi; *(uint32_t*)&g_aol[i1] = lo;
    }
}

// ---------------------------------------------------------------------------
extern "C" void kernel_launch(void* const* d_in, const int* in_sizes, int n_in,
                              void* d_out, int out_size) {
    const float* query     = (const float*)d_in[0];
    const float* mask      = (const float*)d_in[1];
    const float* W_qkv     = (const float*)d_in[2];
    const float* magnitude = (const float*)d_in[3];
    const float* W_loraA   = (const float*)d_in[4];
    const float* W_loraB   = (const float*)d_in[5];
    const float* W_proj    = (const float*)d_in[6];
    float* out = (float*)d_out;

    cudaFuncSetAttribute(mma_gemm_kernel<0>,
        cudaFuncAttributeMaxDynamicSharedMemorySize, SMEM_GEMM);
    cudaFuncSetAttribute(mma_gemm_kernel<1>,
        cudaFuncAttributeMaxDynamicSharedMemorySize, SMEM_GEMM);
    cudaFuncSetAttribute(attn_mma_kernel,
        cudaFuncAttributeMaxDynamicSharedMemorySize, SMEM_ATTN);

    __nv_bfloat16 *gAh, *gAl, *gBh, *gBl, *gaoh, *gaol;
    cudaGetSymbolAddress((void**)&gAh,  g_Ah);
    cudaGetSymbolAddress((void**)&gAl,  g_Al);
    cudaGetSymbolAddress((void**)&gBh,  g_Bh);
    cudaGetSymbolAddress((void**)&gBl,  g_Bl);
    cudaGetSymbolAddress((void**)&gaoh, g_aoh);
    cudaGetSymbolAddress((void**)&gaol, g_aol);

    // Stage 1: conversions (LoRA folded into qkv weights algebraically)
    split_kernel<<<(Mq * Cq / 4) / 256, 256>>>(query, gAh, gAl);
    transpose_split_qkv_kernel<<<dim3(C3q / 32, Cq / 32), dim3(32, 8)>>>(
        W_qkv, W_loraA, W_loraB, magnitude, gBh, gBl);

    // Stage 2: qkv GEMM (2 CTAs/SM) -> split-bf16 q/k/v (q pre-scaled)
    mma_gemm_kernel<0><<<dim3(C3q / 128, Mq / 64), 128, SMEM_GEMM>>>(gAh, gAl, gBh, gBl, nullptr);

    // Stage 3: attention (2 CTAs/SM, shortened softmax path)
    attn_mma_kernel<<<dim3(Hq, Nq / 64, Bq), 128, SMEM_ATTN>>>(mask);

    // Stage 4: proj GEMM (2 CTAs/SM)
    transpose_split_kernel<<<dim3(Cq / 32, Cq / 32), dim3(32, 8)>>>(W_proj, gBh, gBl, Cq, Cq);
    mma_gemm_kernel<1><<<dim3(Cq / 128, Mq / 64), 128, SMEM_GEMM>>>(gaoh, gaol, gBh, gBl, out);
}

// round 14
// speedup vs baseline: 1.0420x; 1.0420x over previous
#include <cuda_runtime.h>
#include <cuda_bf16.h>
#include <cstdint>
#include <math.h>

// Problem constants
#define Bq   4
#define Nq   2048
#define Cq   1024
#define Hq   16
#define Dq   64
#define Rq   16
#define Mq   (Bq*Nq)          // 8192 rows
#define C3q  (3*Cq)           // 3072
#define SCALEF 0.125f         // 1/sqrt(64)
#define L2E 1.4426950408889634f

// ---------------------------------------------------------------------------
// Device-global scratch
// ---------------------------------------------------------------------------
__device__ __nv_bfloat16 g_qh[Mq*Cq], g_ql[Mq*Cq];    // q (pre-scaled) [B,H,N,D]
__device__ __nv_bfloat16 g_kh[Mq*Cq], g_kl[Mq*Cq];    // k
__device__ __nv_bfloat16 g_vh[Mq*Cq], g_vl[Mq*Cq];    // v
__device__ __nv_bfloat16 g_aoh[Mq*Cq], g_aol[Mq*Cq];  // attn out [B,N,C] split

__device__ __nv_bfloat16 g_Ah[Mq*Cq],  g_Al[Mq*Cq];    // qkv A split [M,K]
__device__ __nv_bfloat16 g_Bh[C3q*Cq], g_Bl[C3q*Cq];   // W^T split [N,K]

// ---------------------------------------------------------------------------
// helpers
// ---------------------------------------------------------------------------
__device__ __forceinline__ uint32_t smem_to_u32(const void* p) {
    uint32_t a;
    asm("{ .reg .u64 t; cvta.to.shared.u64 t, %1; cvt.u32.u64 %0, t; }"
        : "=r"(a) : "l"(p));
    return a;
}
__device__ __forceinline__ void ldsm_x4(uint32_t* r, uint32_t addr) {
    asm volatile("ldmatrix.sync.aligned.m8n8.x4.shared.b16 {%0,%1,%2,%3}, [%4];"
                 : "=r"(r[0]), "=r"(r[1]), "=r"(r[2]), "=r"(r[3]) : "r"(addr));
}
__device__ __forceinline__ void ldsm_x4_t(uint32_t* r, uint32_t addr) {
    asm volatile("ldmatrix.sync.aligned.m8n8.x4.trans.shared.b16 {%0,%1,%2,%3}, [%4];"
                 : "=r"(r[0]), "=r"(r[1]), "=r"(r[2]), "=r"(r[3]) : "r"(addr));
}
__device__ __forceinline__ void mma16816(float* c, const uint32_t* a, const uint32_t* b) {
    asm volatile("mma.sync.aligned.m16n8k16.row.col.f32.bf16.bf16.f32 "
        "{%0,%1,%2,%3}, {%4,%5,%6,%7}, {%8,%9}, {%0,%1,%2,%3};"
        : "+f"(c[0]), "+f"(c[1]), "+f"(c[2]), "+f"(c[3])
        : "r"(a[0]), "r"(a[1]), "r"(a[2]), "r"(a[3]), "r"(b[0]), "r"(b[1]));
}
__device__ __forceinline__ void split2(float x, float y, uint32_t& hi, uint32_t& lo) {
    __nv_bfloat16 hx = __float2bfloat16(x), hy = __float2bfloat16(y);
    __nv_bfloat16 lx = __float2bfloat16(x - __bfloat162float(hx));
    __nv_bfloat16 ly = __float2bfloat16(y - __bfloat162float(hy));
    __nv_bfloat162 H(hx, hy), L(lx, ly);
    hi = *(uint32_t*)&H; lo = *(uint32_t*)&L;
}
__device__ __forceinline__ void cp_async16(uint32_t dst, const void* src) {
    asm volatile("cp.async.cg.shared.global [%0], [%1], 16;"
                 :: "r"(dst), "l"(src) : "memory");
}
__device__ __forceinline__ void cp_commit() {
    asm volatile("cp.async.commit_group;" ::: "memory");
}
template<int N> __device__ __forceinline__ void cp_wait() {
    asm volatile("cp.async.wait_group %0;" :: "n"(N) : "memory");
}
__device__ __forceinline__ float ex2(float x) {
    float y; asm("ex2.approx.f32 %0, %1;" : "=f"(y) : "f"(x)); return y;
}
// swizzled byte offset inside a (128B-row) bf16 tile; ch = 16B chunk 0..7
__device__ __forceinline__ uint32_t swz_bf16(int row, int ch) {
    return (uint32_t)(row * 128 + ((ch ^ (row & 7)) << 4));
}
// swizzled byte offset inside a (256B-row) f32 tile; ch = 16B chunk 0..15
__device__ __forceinline__ uint32_t swz_f32(int row, int ch) {
    return (uint32_t)(row * 256 + (((ch ^ ((row & 7) << 1)) & 15) << 4));
}

// ---------------------------------------------------------------------------
// Conversion kernels
// ---------------------------------------------------------------------------
__global__ void split_kernel(const float* __restrict__ X,
                             __nv_bfloat16* __restrict__ H,
                             __nv_bfloat16* __restrict__ L) {
    int i = blockIdx.x * blockDim.x + threadIdx.x;
    float4 x = ((const float4*)X)[i];
    uint32_t h0, l0, h1, l1;
    split2(x.x, x.y, h0, l0);
    split2(x.z, x.w, h1, l1);
    ((uint32_t*)H)[2*i+0] = h0; ((uint32_t*)H)[2*i+1] = h1;
    ((uint32_t*)L)[2*i+0] = l0; ((uint32_t*)L)[2*i+1] = l1;
}

__global__ void transpose_split_kernel(const float* __restrict__ W,
                                       __nv_bfloat16* __restrict__ BH,
                                       __nv_bfloat16* __restrict__ BL,
                                       int K, int N) {
    __shared__ float tile[32][33];
    int n0 = blockIdx.x * 32, k0 = blockIdx.y * 32;
    int tx = threadIdx.x, ty = threadIdx.y;
#pragma unroll
    for (int i = 0; i < 4; i++)
        tile[ty + i * 8][tx] = W[(size_t)(k0 + ty + i * 8) * N + n0 + tx];
    __syncthreads();
#pragma unroll
    for (int i = 0; i < 4; i++) {
        int nl = ty + i * 8;
        float v = tile[tx][nl];
        __nv_bfloat16 h = __float2bfloat16(v);
        __nv_bfloat16 l = __float2bfloat16(v - __bfloat162float(h));
        size_t o = (size_t)(n0 + nl) * K + k0 + tx;
        BH[o] = h; BL[o] = l;
    }
}

// W_qkv[K,3C] -> [3C,K] transpose + split with LoRA delta folded into q cols
__global__ void transpose_split_qkv_kernel(const float* __restrict__ W,
                                           const float* __restrict__ WA,
                                           const float* __restrict__ WB,
                                           const float* __restrict__ mag,
                                           __nv_bfloat16* __restrict__ BH,
                                           __nv_bfloat16* __restrict__ BL) {
    __shared__ float tile[32][33];
    __shared__ float WAs[32][17];   // [k][r]
    __shared__ float WBs[16][33];   // [r][n] (mag applied)
    int n0 = blockIdx.x * 32, k0 = blockIdx.y * 32;
    int tx = threadIdx.x, ty = threadIdx.y;
    const bool doq = (n0 < Cq);
#pragma unroll
    for (int i = 0; i < 4; i++)
        tile[ty + i * 8][tx] = W[(size_t)(k0 + ty + i * 8) * C3q + n0 + tx];
    if (doq) {
        int fi = ty * 32 + tx;
#pragma unroll
        for (int i = 0; i < 2; i++) {
            int idx = fi + i * 256;
            int kr = idx >> 4, r = idx & 15;
            WAs[kr][r] = WA[(size_t)(k0 + kr) * Rq + r];
            int rr = idx >> 5, nn = idx & 31;
            WBs[rr][nn] = mag[(n0 + nn) >> 6] * WB[(size_t)rr * Cq + n0 + nn];
        }
    }
    __syncthreads();
#pragma unroll
    for (int i = 0; i < 4; i++) {
        int nl = ty + i * 8;
        float v = tile[tx][nl];
        if (doq) {
            float d = 0.f;
#pragma unroll
            for (int r = 0; r < Rq; r++) d += WAs[tx][r] * WBs[r][nl];
            v += d;
        }
        __nv_bfloat16 h = __float2bfloat16(v);
        __nv_bfloat16 l = __float2bfloat16(v - __bfloat162float(h));
        size_t o = (size_t)(n0 + nl) * Cq + k0 + tx;
        BH[o] = h; BL[o] = l;
    }
}

// ---------------------------------------------------------------------------
// mma.sync split-bf16 GEMM, 2 CTAs/SM (R12 structure; q pre-scaled in epilogue)
// ---------------------------------------------------------------------------
#define GSTAGE 49152
#define NKB    16
#define SMEM_GEMM (2 * GSTAGE)              // 98304 B

template<int MODE>
__global__ __launch_bounds__(128, 2) void mma_gemm_kernel(
    const __nv_bfloat16* __restrict__ Ah, const __nv_bfloat16* __restrict__ Al,
    const __nv_bfloat16* __restrict__ Bh, const __nv_bfloat16* __restrict__ Bl,
    float* __restrict__ out)
{
    extern __shared__ char smg[];
    const uint32_t sb = smem_to_u32(smg);

    const int bn = blockIdx.x * 128;
    const int bm = blockIdx.y * 64;
    const int t    = threadIdx.x;
    const int lane = t & 31;
    const int wid  = t >> 5;
    const int wm = wid & 1, wn = wid >> 1;

    const int a_row = lane & 15;
    const int a_ch  = lane >> 4;
    const int b_row = (lane & 7) + ((lane & 16) ? 8 : 0);
    const int b_ch  = (lane & 8) >> 3;

    auto load_stage = [&](int s, int kb) {
        uint32_t sbase = sb + (uint32_t)(s * GSTAGE);
#pragma unroll
        for (int it = 0; it < 4; it++) {
            int idx = t + it * 128;
            int row = idx >> 3, ch = idx & 7;
            size_t ga = (size_t)(bm + row) * Cq + kb * 64 + ch * 8;
            uint32_t o = sbase + swz_bf16(row, ch);
            cp_async16(o,        &Ah[ga]);
            cp_async16(o + 8192, &Al[ga]);
        }
#pragma unroll
        for (int it = 0; it < 8; it++) {
            int idx = t + it * 128;
            int row = idx >> 3, ch = idx & 7;
            size_t gb = (size_t)(bn + row) * Cq + kb * 64 + ch * 8;
            uint32_t o = sbase + 16384 + swz_bf16(row, ch);
            cp_async16(o,         &Bh[gb]);
            cp_async16(o + 16384, &Bl[gb]);
        }
        cp_commit();
    };

    float c[16][4];
#pragma unroll
    for (int i = 0; i < 16; i++)
#pragma unroll
        for (int j = 0; j < 4; j++) c[i][j] = 0.f;

    load_stage(0, 0);

    for (int kb = 0; kb < NKB; kb++) {
        const int s = kb & 1;
        if (kb + 1 < NKB) { load_stage(s ^ 1, kb + 1); cp_wait<1>(); }
        else              { cp_wait<0>(); }
        __syncthreads();

        const uint32_t sbase = sb + (uint32_t)(s * GSTAGE);

#pragma unroll
        for (int kk = 0; kk < 4; kk++) {
            uint32_t ah[2][4], al[2][4];
#pragma unroll
            for (int fm = 0; fm < 2; fm++) {
                uint32_t off = swz_bf16(wm * 32 + fm * 16 + a_row, kk * 2 + a_ch);
                ldsm_x4(ah[fm], sbase + off);
                ldsm_x4(al[fm], sbase + 8192 + off);
            }
#pragma unroll
            for (int fn2 = 0; fn2 < 4; fn2++) {
                uint32_t off = swz_bf16(wn * 64 + fn2 * 16 + b_row, kk * 2 + b_ch);
                uint32_t bh4[4], bl4[4];
                ldsm_x4(bh4, sbase + 16384 + off);
                ldsm_x4(bl4, sbase + 32768 + off);
#pragma unroll
                for (int fm = 0; fm < 2; fm++) {
                    float* c0 = c[fm * 8 + fn2 * 2 + 0];
                    float* c1 = c[fm * 8 + fn2 * 2 + 1];
                    mma16816(c0, ah[fm], &bh4[0]);
                    mma16816(c1, ah[fm], &bh4[2]);
                    mma16816(c0, ah[fm], &bl4[0]);
                    mma16816(c1, ah[fm], &bl4[2]);
                    mma16816(c0, al[fm], &bh4[0]);
                    mma16816(c1, al[fm], &bh4[2]);
                }
            }
        }
        __syncthreads();
    }

    // Epilogue (q gets SCALEF folded in so attention's mask step is an FADD)
#pragma unroll
    for (int fm = 0; fm < 2; fm++) {
#pragma unroll
        for (int fn = 0; fn < 8; fn++) {
            const float* cc = c[fm * 8 + fn];
            int r0  = bm + wm * 32 + fm * 16 + (lane >> 2);
            int col = bn + wn * 64 + fn * 8 + (lane & 3) * 2;
#pragma unroll
            for (int half = 0; half < 2; half++) {
                int m = r0 + half * 8;
                float vx = cc[half * 2 + 0], vy = cc[half * 2 + 1];
                if (MODE == 1) {
                    *(float2*)(out + (size_t)m * Cq + col) = make_float2(vx, vy);
                } else {
                    int sel = col >> 10;
                    int within = col & (Cq - 1);
                    int h = within >> 6, d = within & 63;
                    int b = m >> 11, n = m & (Nq - 1);
                    size_t oidx = ((((size_t)b * Hq + h) * Nq) + n) * Dq + d;
                    if (sel == 0) { vx *= SCALEF; vy *= SCALEF; }
                    uint32_t hi, lo;
                    split2(vx, vy, hi, lo);
                    __nv_bfloat16 *ph, *pl;
                    if (sel == 0)      { ph = g_qh; pl = g_ql; }
                    else if (sel == 1) { ph = g_kh; pl = g_kl; }
                    else               { ph = g_vh; pl = g_vl; }
                    *(uint32_t*)&ph[oidx] = hi;
                    *(uint32_t*)&pl[oidx] = lo;
                }
            }
        }
    }
}

// ---------------------------------------------------------------------------
// Flash attention, split-bf16, 2 CTAs/SM — exact R12 structure (mask added
// AFTER the S MMAs, unconditional rescale, per-lane l). Only deltas vs R12:
// q pre-scaled (mask step = FADD) and exp via ex2+fmaf.
// ---------------------------------------------------------------------------
#define KVB2      8192
#define AQ_BYTES  16384
#define AKV_BYTES (2 * 4 * KVB2)
#define AMSK_OFF  (AQ_BYTES + AKV_BYTES)
#define AMSK_STAGE 16384
#define SMEM_ATTN (AMSK_OFF + 2 * AMSK_STAGE) // 114688 B

__global__ __launch_bounds__(128, 2) void attn_mma_kernel(const float* __restrict__ mask) {
    extern __shared__ char smc[];
    const uint32_t sb    = smem_to_u32(smc);
    const uint32_t sbQh  = sb;
    const uint32_t sbQl  = sb + 8192;
    const uint32_t sbKV  = sb + AQ_BYTES;
    const uint32_t sbMsk = sb + AMSK_OFF;

    const int h  = blockIdx.x, qt = blockIdx.y, b = blockIdx.z;
    const int t    = threadIdx.x;
    const int lane = t & 31;
    const int wid  = t >> 5;

    const size_t base = ((size_t)b * Hq + h) * Nq;
    const float* maskbase = mask + (size_t)b * Nq * Nq + (size_t)(qt * 64) * Nq;

    auto load_stage = [&](int s, int kt) {
#pragma unroll
        for (int it = 0; it < 4; it++) {
            int idx = t + it * 128;
            int row = idx >> 3, ch = idx & 7;
            size_t g = (base + (size_t)(kt * 64 + row)) * Dq + ch * 8;
            uint32_t o = sbKV + (uint32_t)(s * 4 * KVB2) + swz_bf16(row, ch);
            cp_async16(o + 0 * KVB2, &g_kh[g]);
            cp_async16(o + 1 * KVB2, &g_kl[g]);
            cp_async16(o + 2 * KVB2, &g_vh[g]);
            cp_async16(o + 3 * KVB2, &g_vl[g]);
        }
#pragma unroll
        for (int it = 0; it < 8; it++) {
            int idx = t + it * 128;
            int row = idx >> 4, ch = idx & 15;
            const float* src = maskbase + (size_t)row * Nq + kt * 64 + ch * 4;
            uint32_t dst = sbMsk + (uint32_t)(s * AMSK_STAGE) + swz_f32(row, ch);
            cp_async16(dst, src);
        }
        cp_commit();
    };

    load_stage(0, 0);

    const __nv_bfloat16* Qgh = g_qh + (base + (size_t)qt * 64) * Dq;
    const __nv_bfloat16* Qgl = g_ql + (base + (size_t)qt * 64) * Dq;
#pragma unroll
    for (int it = 0; it < 4; it++) {
        int idx = t + it * 128;
        int row = idx >> 3, ch = idx & 7;
        uint32_t o = swz_bf16(row, ch);
        *(uint4*)(smc + o)        = *(const uint4*)&Qgh[row * Dq + ch * 8];
        *(uint4*)(smc + 8192 + o) = *(const uint4*)&Qgl[row * Dq + ch * 8];
    }
    __syncthreads();

    const int a_row = lane & 15;
    const int a_ch  = (lane >> 4);
    uint32_t aQh[4][4], aQl[4][4];
    {
        int qrow = wid * 16 + a_row;
#pragma unroll
        for (int kk = 0; kk < 4; kk++) {
            uint32_t off = swz_bf16(qrow, kk * 2 + a_ch);
            ldsm_x4(aQh[kk], sbQh + off);
            ldsm_x4(aQl[kk], sbQl + off);
        }
    }

    const int b_row = (lane & 7) + ((lane & 16) ? 8 : 0);
    const int b_ch  = (lane & 8) >> 3;
    const int v_row = lane & 15;
    const int v_ch  = (lane & 16) ? 1 : 0;

    float o[8][4];
#pragma unroll
    for (int i = 0; i < 8; i++)
#pragma unroll
        for (int j = 0; j < 4; j++) o[i][j] = 0.f;
    float m0 = -1e30f, m1 = -1e30f, l0 = 0.f, l1 = 0.f;

    const int rloc0 = wid * 16 + (lane >> 2);
    const int mcol  = 2 * (lane & 3);

    for (int kt = 0; kt < Nq / 64; kt++) {
        const int s = kt & 1;
        if (kt + 1 < Nq / 64) { load_stage(s ^ 1, kt + 1); cp_wait<1>(); }
        else                  { cp_wait<0>(); }
        __syncthreads();

        const uint32_t sbKh = sbKV + (uint32_t)(s * 4 * KVB2);
        const uint32_t sbKl = sbKh + KVB2;
        const uint32_t sbVh = sbKh + 2 * KVB2;
        const uint32_t sbVl = sbKh + 3 * KVB2;
        const char* mskC = smc + AMSK_OFF + s * AMSK_STAGE;

        // S = Q K^T (16 x 64 per warp), 3-term split (fn2 outer, R8 order)
        float c[8][4];
#pragma unroll
        for (int i = 0; i < 8; i++)
#pragma unroll
            for (int j = 0; j < 4; j++) c[i][j] = 0.f;
#pragma unroll
        for (int fn2 = 0; fn2 < 4; fn2++) {
#pragma unroll
            for (int kk = 0; kk < 4; kk++) {
                uint32_t off = swz_bf16(fn2 * 16 + b_row, kk * 2 + b_ch);
                uint32_t bh4[4], bl4[4];
                ldsm_x4(bh4, sbKh + off);
                ldsm_x4(bl4, sbKl + off);
                float* c0 = c[fn2 * 2 + 0];
                float* c1 = c[fn2 * 2 + 1];
                mma16816(c0, aQh[kk], &bh4[0]);
                mma16816(c1, aQh[kk], &bh4[2]);
                mma16816(c0, aQh[kk], &bl4[0]);
                mma16816(c1, aQh[kk], &bl4[2]);
                mma16816(c0, aQl[kk], &bh4[0]);
                mma16816(c1, aQl[kk], &bh4[2]);
            }
        }

        // mask add (q pre-scaled: pure FADD)
#pragma unroll
        for (int f = 0; f < 8; f++) {
            int col = f * 8 + mcol;
            int ch  = col >> 2;
            int wo  = (col & 3) * 4;
            float2 mk0 = *(const float2*)(mskC + swz_f32(rloc0,     ch) + wo);
            float2 mk1 = *(const float2*)(mskC + swz_f32(rloc0 + 8, ch) + wo);
            c[f][0] += mk0.x;
            c[f][1] += mk0.y;
            c[f][2] += mk1.x;
            c[f][3] += mk1.y;
        }

        // online softmax (max over quad; l per-lane, reduced at end)
        float rm0 = -1e30f, rm1 = -1e30f;
#pragma unroll
        for (int f = 0; f < 8; f++) {
            rm0 = fmaxf(rm0, fmaxf(c[f][0], c[f][1]));
            rm1 = fmaxf(rm1, fmaxf(c[f][2], c[f][3]));
        }
        rm0 = fmaxf(rm0, __shfl_xor_sync(0xffffffffu, rm0, 1));
        rm0 = fmaxf(rm0, __shfl_xor_sync(0xffffffffu, rm0, 2));
        rm1 = fmaxf(rm1, __shfl_xor_sync(0xffffffffu, rm1, 1));
        rm1 = fmaxf(rm1, __shfl_xor_sync(0xffffffffu, rm1, 2));
        float nm0 = fmaxf(m0, rm0), nm1 = fmaxf(m1, rm1);
        float b0 = nm0 * L2E, b1 = nm1 * L2E;
        float sc0 = ex2(fmaf(m0, L2E, -b0));
        float sc1 = ex2(fmaf(m1, L2E, -b1));
        float s0 = 0.f, s1 = 0.f;
#pragma unroll
        for (int f = 0; f < 8; f++) {
            c[f][0] = ex2(fmaf(c[f][0], L2E, -b0));
            c[f][1] = ex2(fmaf(c[f][1], L2E, -b0));
            c[f][2] = ex2(fmaf(c[f][2], L2E, -b1));
            c[f][3] = ex2(fmaf(c[f][3], L2E, -b1));
            s0 += c[f][0] + c[f][1];
            s1 += c[f][2] + c[f][3];
        }
        l0 = l0 * sc0 + s0; m0 = nm0;
        l1 = l1 * sc1 + s1; m1 = nm1;
#pragma unroll
        for (int f = 0; f < 8; f++) {
            o[f][0] *= sc0; o[f][1] *= sc0;
            o[f][2] *= sc1; o[f][3] *= sc1;
        }

        // O += P V
#pragma unroll
        for (int kk = 0; kk < 4; kk++) {
            uint32_t pah[4], pal[4];
            split2(c[2*kk  ][0], c[2*kk  ][1], pah[0], pal[0]);
            split2(c[2*kk  ][2], c[2*kk  ][3], pah[1], pal[1]);
            split2(c[2*kk+1][0], c[2*kk+1][1], pah[2], pal[2]);
            split2(c[2*kk+1][2], c[2*kk+1][3], pah[3], pal[3]);
#pragma unroll
            for (int nn = 0; nn < 4; nn++) {
                uint32_t off = swz_bf16(kk * 16 + v_row, nn * 2 + v_ch);
                uint32_t vh4[4], vl4[4];
                ldsm_x4_t(vh4, sbVh + off);
                ldsm_x4_t(vl4, sbVl + off);
                float* o0 = o[nn * 2 + 0];
                float* o1 = o[nn * 2 + 1];
                mma16816(o0, pah, &vh4[0]);
                mma16816(o1, pah, &vh4[2]);
                mma16816(o0, pah, &vl4[0]);
                mma16816(o1, pah, &vl4[2]);
                mma16816(o0, pal, &vh4[0]);
                mma16816(o1, pal, &vh4[2]);
            }
        }
        __syncthreads();
    }

    // Final quad-reduce of l
    l0 += __shfl_xor_sync(0xffffffffu, l0, 1);
    l0 += __shfl_xor_sync(0xffffffffu, l0, 2);
    l1 += __shfl_xor_sync(0xffffffffu, l1, 1);
    l1 += __shfl_xor_sync(0xffffffffu, l1, 2);

    // Epilogue
    float inv0 = 1.0f / l0, inv1 = 1.0f / l1;
    int n0r = qt * 64 + wid * 16 + (lane >> 2);
#pragma unroll
    for (int f = 0; f < 8; f++) {
        int colc = h * Dq + f * 8 + 2 * (lane & 3);
        size_t i0 = ((size_t)(b * Nq + n0r)) * Cq + colc;
        size_t i1 = ((size_t)(b * Nq + n0r + 8)) * Cq + colc;
        uint32_t hi, lo;
        split2(o[f][0] * inv0, o[f][1] * inv0, hi, lo);
        *(uint32_t*)&g_aoh[i0] = hi; *(uint32_t*)&g_aol[i0] = lo;
        split2(o[f][2] * inv1, o[f][3] * inv1, hi, lo);
        *(uint32_t*)&g_aoh[i1] = hi; *(uint32_t*)&g_aol[i1] = lo;
    }
}

// ---------------------------------------------------------------------------
extern "C" void kernel_launch(void* const* d_in, const int* in_sizes, int n_in,
                              void* d_out, int out_size) {
    const float* query     = (const float*)d_in[0];
    const float* mask      = (const float*)d_in[1];
    const float* W_qkv     = (const float*)d_in[2];
    const float* magnitude = (const float*)d_in[3];
    const float* W_loraA   = (const float*)d_in[4];
    const float* W_loraB   = (const float*)d_in[5];
    const float* W_proj    = (const float*)d_in[6];
    float* out = (float*)d_out;

    cudaFuncSetAttribute(mma_gemm_kernel<0>,
        cudaFuncAttributeMaxDynamicSharedMemorySize, SMEM_GEMM);
    cudaFuncSetAttribute(mma_gemm_kernel<1>,
        cudaFuncAttributeMaxDynamicSharedMemorySize, SMEM_GEMM);
    cudaFuncSetAttribute(attn_mma_kernel,
        cudaFuncAttributeMaxDynamicSharedMemorySize, SMEM_ATTN);

    __nv_bfloat16 *gAh, *gAl, *gBh, *gBl, *gaoh, *gaol;
    cudaGetSymbolAddress((void**)&gAh,  g_Ah);
    cudaGetSymbolAddress((void**)&gAl,  g_Al);
    cudaGetSymbolAddress((void**)&gBh,  g_Bh);
    cudaGetSymbolAddress((void**)&gBl,  g_Bl);
    cudaGetSymbolAddress((void**)&gaoh, g_aoh);
    cudaGetSymbolAddress((void**)&gaol, g_aol);

    // Stage 1: conversions (LoRA folded into qkv weights algebraically)
    split_kernel<<<(Mq * Cq / 4) / 256, 256>>>(query, gAh, gAl);
    transpose_split_qkv_kernel<<<dim3(C3q / 32, Cq / 32), dim3(32, 8)>>>(
        W_qkv, W_loraA, W_loraB, magnitude, gBh, gBl);

    // Stage 2: qkv GEMM (2 CTAs/SM) -> split-bf16 q/k/v (q pre-scaled)
    mma_gemm_kernel<0><<<dim3(C3q / 128, Mq / 64), 128, SMEM_GEMM>>>(gAh, gAl, gBh, gBl, nullptr);

    // Stage 3: attention (2 CTAs/SM, R12 structure)
    attn_mma_kernel<<<dim3(Hq, Nq / 64, Bq), 128, SMEM_ATTN>>>(mask);

    // Stage 4: proj GEMM (2 CTAs/SM)
    transpose_split_kernel<<<dim3(Cq / 32, Cq / 32), dim3(32, 8)>>>(W_proj, gBh, gBl, Cq, Cq);
    mma_gemm_kernel<1><<<dim3(Cq / 128, Mq / 64), 128, SMEM_GEMM>>>(gaoh, gaol, gBh, gBl, out);
}